// round 13
// baseline (speedup 1.0000x reference)
#include <cuda_runtime.h>
#include <cuda_bf16.h>
#include <cstdint>

// Problem constants: T=1024, H=2048, F=768, E=64, K=8
#define T_TOK   1024
#define H_DIM   2048
#define F_DIM   768
#define F2_DIM  1536
#define NEXP    64
#define TOPK    8
#define NPAIR   (T_TOK * TOPK)
#define TS      32                   // m-tile rows
#define MAXTILES 320                 // worst case: 64 + 8192/32 = 320
#define MAXROWS  (MAXTILES * TS)     // 10240

// ---------------------------------------------------------------------------
// Device-global scratch (allocation-free per harness rules)
// ---------------------------------------------------------------------------
__device__ int   g_cnt[NEXP];
__device__ int   g_tilebase[NEXP];
__device__ int   g_ntiles;
__device__ int   g_tile_expert[MAXTILES];
__device__ int   g_rowtok[MAXROWS];
__device__ int   g_slot[NPAIR];

__device__ __align__(256) __nv_bfloat16 g_Ah [(size_t)MAXROWS * H_DIM];
__device__ __align__(256) __nv_bfloat16 g_Al [(size_t)MAXROWS * H_DIM];
__device__ __align__(256) __nv_bfloat16 g_acth[(size_t)MAXROWS * F_DIM];
__device__ __align__(256) __nv_bfloat16 g_actl[(size_t)MAXROWS * F_DIM];
__device__ __align__(256) float g_y2 [(size_t)MAXROWS * H_DIM];

// ---------------------------------------------------------------------------
// Portable PTX helpers
// ---------------------------------------------------------------------------
__device__ __forceinline__ uint32_t smem_u32(const void* p) {
    uint32_t a;
    asm("{ .reg .u64 t; cvta.to.shared.u64 t, %1; cvt.u32.u64 %0, t; }" : "=r"(a) : "l"(p));
    return a;
}
#define CP_ASYNC16(dst_u32, src) \
    asm volatile("cp.async.cg.shared.global [%0], [%1], 16;" :: "r"(dst_u32), "l"(src))
#define CP_COMMIT() asm volatile("cp.async.commit_group;" ::: "memory")
#define CP_WAIT(n)  asm volatile("cp.async.wait_group %0;" :: "n"(n) : "memory")

#define LDSM4(r, addr) \
    asm volatile("ldmatrix.sync.aligned.m8n8.x4.shared.b16 {%0,%1,%2,%3}, [%4];" \
        : "=r"((r)[0]), "=r"((r)[1]), "=r"((r)[2]), "=r"((r)[3]) : "r"(addr))

#define MMA_BF16(d, a, b0v, b1v) \
    asm volatile("mma.sync.aligned.m16n8k16.row.col.f32.bf16.bf16.f32 " \
        "{%0,%1,%2,%3}, {%4,%5,%6,%7}, {%8,%9}, {%0,%1,%2,%3};" \
        : "+f"((d)[0]), "+f"((d)[1]), "+f"((d)[2]), "+f"((d)[3]) \
        : "r"((a)[0]), "r"((a)[1]), "r"((a)[2]), "r"((a)[3]), "r"(b0v), "r"(b1v))

#define STSV4(addr, r0, r1, r2, r3) \
    asm volatile("st.shared.v4.b32 [%0], {%1,%2,%3,%4};" \
        :: "r"(addr), "r"(r0), "r"(r1), "r"(r2), "r"(r3) : "memory")

// ---------------------------------------------------------------------------
// bf16 split helpers
// ---------------------------------------------------------------------------
__device__ __forceinline__ uint32_t pk(__nv_bfloat16 a, __nv_bfloat16 b) {
    __nv_bfloat162 t(a, b);
    return *reinterpret_cast<uint32_t*>(&t);
}
__device__ __forceinline__ void split4(float4 v, uint2& hi, uint2& lo) {
    __nv_bfloat16 h0 = __float2bfloat16(v.x), h1 = __float2bfloat16(v.y);
    __nv_bfloat16 h2 = __float2bfloat16(v.z), h3 = __float2bfloat16(v.w);
    __nv_bfloat16 l0 = __float2bfloat16(v.x - __bfloat162float(h0));
    __nv_bfloat16 l1 = __float2bfloat16(v.y - __bfloat162float(h1));
    __nv_bfloat16 l2 = __float2bfloat16(v.z - __bfloat162float(h2));
    __nv_bfloat16 l3 = __float2bfloat16(v.w - __bfloat162float(h3));
    hi = make_uint2(pk(h0, h1), pk(h2, h3));
    lo = make_uint2(pk(l0, l1), pk(l2, l3));
}

// ---------------------------------------------------------------------------
// Dispatch (counting sort, deterministic)
// ---------------------------------------------------------------------------
__global__ void k_init() {
    int i = blockIdx.x * blockDim.x + threadIdx.x;
    if (i < MAXROWS) g_rowtok[i] = -1;
    if (i < NEXP)    g_cnt[i] = 0;
}
__global__ void k_count(const int* __restrict__ ids) {
    int p = blockIdx.x * blockDim.x + threadIdx.x;
    if (p < NPAIR) atomicAdd(&g_cnt[ids[p]], 1);
}
__global__ void k_scan() {
    if (threadIdx.x != 0 || blockIdx.x != 0) return;
    int base = 0;
    for (int e = 0; e < NEXP; e++) {
        g_tilebase[e] = base;
        int nt = (g_cnt[e] + TS - 1) / TS;
        for (int i = 0; i < nt; i++) g_tile_expert[base / TS + i] = e;
        base += nt * TS;
    }
    g_ntiles = base / TS;
}
__global__ void k_scatter(const int* __restrict__ ids) {
    const int e = blockIdx.x, lane = threadIdx.x;
    int off = g_tilebase[e];
    for (int base = 0; base < NPAIR; base += 32) {
        int p = base + lane;
        bool m = (ids[p] == e);
        unsigned mask = __ballot_sync(0xffffffffu, m);
        if (m) {
            int r = off + __popc(mask & ((1u << lane) - 1u));
            g_rowtok[r] = p >> 3;
            g_slot[p] = r;
        }
        off += __popc(mask);
    }
}

// ---------------------------------------------------------------------------
// Gather + split hidden rows into padded [rows, H] bf16 hi/lo
// ---------------------------------------------------------------------------
__global__ void k_prepA(const float* __restrict__ hidden) {
    int idx = blockIdx.x * blockDim.x + threadIdx.x;   // over MAXROWS * 512
    int r  = idx >> 9;
    int c4 = idx & 511;
    if (r >= g_ntiles * TS) return;
    int tok = g_rowtok[r];
    float4 v = (tok >= 0) ? ((const float4*)hidden)[(size_t)tok * 512 + c4]
                          : make_float4(0.f, 0.f, 0.f, 0.f);
    uint2 h, l;
    split4(v, h, l);
    ((uint2*)g_Ah)[(size_t)r * 512 + c4] = h;
    ((uint2*)g_Al)[(size_t)r * 512 + c4] = l;
}

// ---------------------------------------------------------------------------
// HMMA grouped GEMM, 32x128 C-tile, 128 threads = 4 warps (1m x 4n),
// warp tile 32x32, BK=32, 2-stage smem (80B-stride rows, ldmatrix-clean).
// B is RAW FP32 weights: LDG.128 reg-double-buffered, split hi/lo in regs,
// STS'd to smem. 3-term bf16x3: AhBh + AhBl + AlBh, fp32 accum.
// GATEUP=true (GEMM1): B rows interleaved gate/up; epilogue computes
// silu(gate)*up and writes bf16 hi/lo activations directly.
// GATEUP=false (GEMM2): plain fp32 C output.
// ---------------------------------------------------------------------------
#define BUF_A   2560               //  32 rows * 80 B
#define BUF_B   10240              // 128 rows * 80 B
#define OFF_AH  0
#define OFF_AL  BUF_A
#define OFF_BH  (2 * BUF_A)
#define OFF_BL  (2 * BUF_A + BUF_B)
#define STAGE_B (2 * BUF_A + 2 * BUF_B)   // 25600
#define GEMM_SMEM (2 * STAGE_B)           // 51200

template<int NK, bool GATEUP>
__global__ __launch_bounds__(128) void hmma_gemm(
    const __nv_bfloat16* __restrict__ Ah, const __nv_bfloat16* __restrict__ Al, int lda,
    const float* __restrict__ B, size_t bstride, int ldb,
    float* __restrict__ C, int ldc,
    __nv_bfloat16* __restrict__ Oh, __nv_bfloat16* __restrict__ Ol)
{
    const int mt = blockIdx.y;
    if (mt >= g_ntiles) return;
    const int e  = g_tile_expert[mt];
    const int n0 = blockIdx.x * 128;

    extern __shared__ char smem[];
    const uint32_t sb = smem_u32(smem);
    const int tid  = threadIdx.x;
    const int wn   = tid >> 5, lane = tid & 31;

    // A loader: row = tid>>2 (0..31), 16B chunk q = tid&3
    const int arow = tid >> 2, aq = tid & 3;
    const __nv_bfloat16* pAh = Ah + (size_t)(mt * TS + arow) * lda + aq * 8;
    const __nv_bfloat16* pAl = Al + (size_t)(mt * TS + arow) * lda + aq * 8;
    const uint32_t adst = (uint32_t)arow * 80 + (uint32_t)aq * 16;

    // B loader (fp32): one full BK=32 row per thread; gate/up interleave for GEMM1
    const int nn = n0 + tid;                       // C column this thread loads
    const int w1row = GATEUP ? ((nn >> 1) + (nn & 1) * F_DIM) : nn;
    const float* pB = B + (size_t)e * bstride + (size_t)w1row * ldb;
    const uint32_t bdst = (uint32_t)tid * 80;

#define LOAD_A(s, k0) do {                                                      \
    uint32_t _g = sb + (s) * STAGE_B;                                           \
    CP_ASYNC16(_g + OFF_AH + adst, pAh + (k0));                                 \
    CP_ASYNC16(_g + OFF_AL + adst, pAl + (k0));                                 \
    CP_COMMIT();                                                                \
} while (0)

#define LOAD_B(dst, k0) do {                                                    \
    _Pragma("unroll")                                                           \
    for (int _c = 0; _c < 8; _c++) {                                            \
        float4 _t = *(const float4*)(pB + (k0) + _c * 4);                       \
        dst[4*_c] = _t.x; dst[4*_c+1] = _t.y; dst[4*_c+2] = _t.z; dst[4*_c+3] = _t.w; \
    }                                                                           \
} while (0)

#define CONV_STS(s, bv) do {                                                    \
    uint32_t _g = sb + (s) * STAGE_B;                                           \
    uint32_t _hb[16], _lb[16];                                                  \
    _Pragma("unroll")                                                           \
    for (int _i = 0; _i < 16; _i++) {                                           \
        float _x = bv[2 * _i], _y = bv[2 * _i + 1];                             \
        __nv_bfloat16 _hx = __float2bfloat16(_x), _hy = __float2bfloat16(_y);   \
        _hb[_i] = pk(_hx, _hy);                                                 \
        _lb[_i] = pk(__float2bfloat16(_x - __bfloat162float(_hx)),              \
                     __float2bfloat16(_y - __bfloat162float(_hy)));             \
    }                                                                           \
    _Pragma("unroll")                                                           \
    for (int _c = 0; _c < 4; _c++) {                                            \
        STSV4(_g + OFF_BH + bdst + _c * 16, _hb[4*_c], _hb[4*_c+1], _hb[4*_c+2], _hb[4*_c+3]); \
        STSV4(_g + OFF_BL + bdst + _c * 16, _lb[4*_c], _lb[4*_c+1], _lb[4*_c+2], _lb[4*_c+3]); \
    }                                                                           \
} while (0)

    // ldmatrix lane offsets (within a 16x16 tile base), stride 80B
    const uint32_t aoff = (uint32_t)((((lane >> 3) & 1) * 8 + (lane & 7)) * 80 + (lane >> 4) * 16);
    const uint32_t boff = (uint32_t)(((lane >> 4) * 8 + (lane & 7)) * 80 + ((lane >> 3) & 1) * 16);

    float acc[2][4][4];
#pragma unroll
    for (int i = 0; i < 2; i++)
#pragma unroll
        for (int j = 0; j < 4; j++)
#pragma unroll
            for (int q = 0; q < 4; q++) acc[i][j][q] = 0.f;

    float bcur[32], bnxt[32];
    LOAD_B(bcur, 0);
    LOAD_A(0, 0);

    for (int kt = 0; kt < NK; kt++) {
        const int s = kt & 1;
        if (kt + 1 < NK) {
            LOAD_B(bnxt, (kt + 1) * 32);
            LOAD_A((kt + 1) & 1, (kt + 1) * 32);
            CP_WAIT(1);
        } else {
            CP_WAIT(0);
        }
        CONV_STS(s, bcur);
        __syncthreads();

        const uint32_t stg = sb + s * STAGE_B;
#pragma unroll
        for (int kk = 0; kk < 2; kk++) {
            const uint32_t ko = (uint32_t)kk * 32;
            uint32_t ah[2][4], al[2][4];
#pragma unroll
            for (int i = 0; i < 2; i++) {
                uint32_t ta = (uint32_t)(i * 16) * 80 + ko;
                LDSM4(ah[i], stg + OFF_AH + ta + aoff);
                LDSM4(al[i], stg + OFF_AL + ta + aoff);
            }
            uint32_t bh[2][4], bl[2][4];
#pragma unroll
            for (int j = 0; j < 2; j++) {
                uint32_t tb = (uint32_t)(wn * 32 + j * 16) * 80 + ko;
                LDSM4(bh[j], stg + OFF_BH + tb + boff);
                LDSM4(bl[j], stg + OFF_BL + tb + boff);
            }
#pragma unroll
            for (int i = 0; i < 2; i++)
#pragma unroll
                for (int j = 0; j < 2; j++)
#pragma unroll
                    for (int s2 = 0; s2 < 2; s2++) {
                        MMA_BF16(acc[i][j * 2 + s2], ah[i], bh[j][2 * s2], bh[j][2 * s2 + 1]);
                        MMA_BF16(acc[i][j * 2 + s2], ah[i], bl[j][2 * s2], bl[j][2 * s2 + 1]);
                        MMA_BF16(acc[i][j * 2 + s2], al[i], bh[j][2 * s2], bh[j][2 * s2 + 1]);
                    }
        }
        __syncthreads();
#pragma unroll
        for (int i = 0; i < 32; i++) bcur[i] = bnxt[i];
    }
#undef LOAD_A
#undef LOAD_B
#undef CONV_STS

    const int r  = lane >> 2;
    const int c2 = (lane & 3) * 2;
    if (GATEUP) {
        // fused SiLU: cols (even, odd) = (gate_f, up_f), f = nn>>1
#pragma unroll
        for (int i = 0; i < 2; i++)
#pragma unroll
            for (int j = 0; j < 2; j++)
#pragma unroll
                for (int s2 = 0; s2 < 2; s2++) {
                    const float* q = acc[i][j * 2 + s2];
                    int col = n0 + wn * 32 + j * 16 + s2 * 8 + c2;
                    int f = col >> 1;
                    int row = mt * TS + i * 16 + r;
                    float g0 = q[0], u0 = q[1];
                    float h0 = (g0 / (1.f + __expf(-g0))) * u0;
                    float g1 = q[2], u1 = q[3];
                    float h1 = (g1 / (1.f + __expf(-g1))) * u1;
                    __nv_bfloat16 hh0 = __float2bfloat16(h0);
                    __nv_bfloat16 hh1 = __float2bfloat16(h1);
                    Oh[(size_t)row * F_DIM + f] = hh0;
                    Ol[(size_t)row * F_DIM + f] = __float2bfloat16(h0 - __bfloat162float(hh0));
                    Oh[(size_t)(row + 8) * F_DIM + f] = hh1;
                    Ol[(size_t)(row + 8) * F_DIM + f] = __float2bfloat16(h1 - __bfloat162float(hh1));
                }
    } else {
#pragma unroll
        for (int i = 0; i < 2; i++)
#pragma unroll
            for (int j = 0; j < 2; j++)
#pragma unroll
                for (int s2 = 0; s2 < 2; s2++) {
                    float* p = C + (size_t)(mt * TS + i * 16 + r) * ldc
                                 + n0 + wn * 32 + j * 16 + s2 * 8 + c2;
                    p[0] = acc[i][j * 2 + s2][0];
                    p[1] = acc[i][j * 2 + s2][1];
                    float* p2 = p + 8 * ldc;
                    p2[0] = acc[i][j * 2 + s2][2];
                    p2[1] = acc[i][j * 2 + s2][3];
                }
    }
}

// ---------------------------------------------------------------------------
// Combine: out[t][h] = sum_k tw[t,k] * y2[slot[t,k]][h]
// ---------------------------------------------------------------------------
__global__ void combine_kernel(const float* __restrict__ tw, float* __restrict__ out) {
    int idx = blockIdx.x * blockDim.x + threadIdx.x;
    int t  = idx / (H_DIM / 4);
    int hq = idx - t * (H_DIM / 4);
    if (t >= T_TOK) return;
    float4 acc = make_float4(0.f, 0.f, 0.f, 0.f);
#pragma unroll
    for (int k = 0; k < TOPK; k++) {
        int   s = g_slot[t * TOPK + k];
        float w = tw[t * TOPK + k];
        float4 v = *(const float4*)&g_y2[(size_t)s * H_DIM + hq * 4];
        acc.x += w * v.x; acc.y += w * v.y; acc.z += w * v.z; acc.w += w * v.w;
    }
    *(float4*)&out[(size_t)t * H_DIM + hq * 4] = acc;
}

// ---------------------------------------------------------------------------
extern "C" void kernel_launch(void* const* d_in, const int* in_sizes, int n_in,
                              void* d_out, int out_size) {
    const float* hidden = (const float*)d_in[0];
    const float* tw     = (const float*)d_in[1];
    const int*   ids    = (const int*)d_in[2];
    const float* w1     = (const float*)d_in[3];
    const float* w2     = (const float*)d_in[4];
    float*       out    = (float*)d_out;

    static void *p_Ah, *p_Al, *p_ah, *p_al, *p_y2;
    cudaGetSymbolAddress(&p_Ah, g_Ah);
    cudaGetSymbolAddress(&p_Al, g_Al);
    cudaGetSymbolAddress(&p_ah, g_acth);
    cudaGetSymbolAddress(&p_al, g_actl);
    cudaGetSymbolAddress(&p_y2, g_y2);

    cudaFuncSetAttribute(hmma_gemm<H_DIM / 32, true>,  cudaFuncAttributeMaxDynamicSharedMemorySize, GEMM_SMEM);
    cudaFuncSetAttribute(hmma_gemm<F_DIM / 32, false>, cudaFuncAttributeMaxDynamicSharedMemorySize, GEMM_SMEM);

    // dispatch + activation prep
    k_init<<<MAXROWS / 256, 256>>>();
    k_count<<<NPAIR / 256, 256>>>(ids);
    k_scan<<<1, 32>>>();
    k_scatter<<<NEXP, 32>>>(ids);
    k_prepA<<<MAXROWS * 512 / 256, 256>>>(hidden);

    // GEMM1 (+fused SiLU): act = silu(gate)*up from A @ w1^T, gate/up interleaved
    hmma_gemm<H_DIM / 32, true><<<dim3(F2_DIM / 128, MAXTILES), 128, GEMM_SMEM>>>(
        (const __nv_bfloat16*)p_Ah, (const __nv_bfloat16*)p_Al, H_DIM,
        w1, (size_t)F2_DIM * H_DIM, H_DIM, nullptr, 0,
        (__nv_bfloat16*)p_ah, (__nv_bfloat16*)p_al);

    // GEMM2: y2 = act @ w2^T  (K = 768; B = raw fp32 w2, split in-kernel)
    hmma_gemm<F_DIM / 32, false><<<dim3(H_DIM / 128, MAXTILES), 128, GEMM_SMEM>>>(
        (const __nv_bfloat16*)p_ah, (const __nv_bfloat16*)p_al, F_DIM,
        w2, (size_t)H_DIM * F_DIM, F_DIM, (float*)p_y2, H_DIM, nullptr, nullptr);

    combine_kernel<<<(T_TOK * H_DIM / 4 + 255) / 256, 256>>>(tw, out);
}

// round 16
// speedup vs baseline: 1.5833x; 1.5833x over previous
#include <cuda_runtime.h>
#include <cuda_bf16.h>
#include <cstdint>

// Problem constants: T=1024, H=2048, F=768, E=64, K=8
#define T_TOK   1024
#define H_DIM   2048
#define F_DIM   768
#define F2_DIM  1536
#define NEXP    64
#define TOPK    8
#define NPAIR   (T_TOK * TOPK)
#define TS      64                   // m-tile rows (R11 sweet spot: B-traffic vs padding)
#define MAXTILES 256                 // worst case: 64 + 8192/64 = 192
#define MAXROWS  16384

// ---------------------------------------------------------------------------
// Device-global scratch (allocation-free per harness rules)
// ---------------------------------------------------------------------------
__device__ int   g_cnt[NEXP];
__device__ int   g_tilebase[NEXP];
__device__ int   g_ntiles;
__device__ int   g_tile_expert[MAXTILES];
__device__ int   g_rowtok[MAXROWS];
__device__ int   g_slot[NPAIR];

__device__ __align__(256) __nv_bfloat16 g_Ah [(size_t)MAXROWS * H_DIM];
__device__ __align__(256) __nv_bfloat16 g_Al [(size_t)MAXROWS * H_DIM];
__device__ __align__(256) __nv_bfloat16 g_acth[(size_t)MAXROWS * F_DIM];
__device__ __align__(256) __nv_bfloat16 g_actl[(size_t)MAXROWS * F_DIM];
__device__ __align__(256) float g_y2 [(size_t)MAXROWS * H_DIM];

// ---------------------------------------------------------------------------
// Portable PTX helpers
// ---------------------------------------------------------------------------
__device__ __forceinline__ uint32_t smem_u32(const void* p) {
    uint32_t a;
    asm("{ .reg .u64 t; cvta.to.shared.u64 t, %1; cvt.u32.u64 %0, t; }" : "=r"(a) : "l"(p));
    return a;
}
#define CP_ASYNC16(dst_u32, src) \
    asm volatile("cp.async.cg.shared.global [%0], [%1], 16;" :: "r"(dst_u32), "l"(src))
#define CP_COMMIT() asm volatile("cp.async.commit_group;" ::: "memory")
#define CP_WAIT(n)  asm volatile("cp.async.wait_group %0;" :: "n"(n) : "memory")

#define LDSM4(r, addr) \
    asm volatile("ldmatrix.sync.aligned.m8n8.x4.shared.b16 {%0,%1,%2,%3}, [%4];" \
        : "=r"((r)[0]), "=r"((r)[1]), "=r"((r)[2]), "=r"((r)[3]) : "r"(addr))

#define MMA_BF16(d, a, b0v, b1v) \
    asm volatile("mma.sync.aligned.m16n8k16.row.col.f32.bf16.bf16.f32 " \
        "{%0,%1,%2,%3}, {%4,%5,%6,%7}, {%8,%9}, {%0,%1,%2,%3};" \
        : "+f"((d)[0]), "+f"((d)[1]), "+f"((d)[2]), "+f"((d)[3]) \
        : "r"((a)[0]), "r"((a)[1]), "r"((a)[2]), "r"((a)[3]), "r"(b0v), "r"(b1v))

#define STSV4(addr, r0, r1, r2, r3) \
    asm volatile("st.shared.v4.b32 [%0], {%1,%2,%3,%4};" \
        :: "r"(addr), "r"(r0), "r"(r1), "r"(r2), "r"(r3) : "memory")

// ---------------------------------------------------------------------------
// bf16 split helpers
// ---------------------------------------------------------------------------
__device__ __forceinline__ uint32_t pk(__nv_bfloat16 a, __nv_bfloat16 b) {
    __nv_bfloat162 t(a, b);
    return *reinterpret_cast<uint32_t*>(&t);
}
__device__ __forceinline__ void split4(float4 v, uint2& hi, uint2& lo) {
    __nv_bfloat16 h0 = __float2bfloat16(v.x), h1 = __float2bfloat16(v.y);
    __nv_bfloat16 h2 = __float2bfloat16(v.z), h3 = __float2bfloat16(v.w);
    __nv_bfloat16 l0 = __float2bfloat16(v.x - __bfloat162float(h0));
    __nv_bfloat16 l1 = __float2bfloat16(v.y - __bfloat162float(h1));
    __nv_bfloat16 l2 = __float2bfloat16(v.z - __bfloat162float(h2));
    __nv_bfloat16 l3 = __float2bfloat16(v.w - __bfloat162float(h3));
    hi = make_uint2(pk(h0, h1), pk(h2, h3));
    lo = make_uint2(pk(l0, l1), pk(l2, l3));
}

// ---------------------------------------------------------------------------
// Dispatch (counting sort, deterministic)
// ---------------------------------------------------------------------------
__global__ void k_init() {
    int i = blockIdx.x * blockDim.x + threadIdx.x;
    if (i < MAXROWS) g_rowtok[i] = -1;
    if (i < NEXP)    g_cnt[i] = 0;
}
__global__ void k_count(const int* __restrict__ ids) {
    int p = blockIdx.x * blockDim.x + threadIdx.x;
    if (p < NPAIR) atomicAdd(&g_cnt[ids[p]], 1);
}
__global__ void k_scan() {
    if (threadIdx.x != 0 || blockIdx.x != 0) return;
    int base = 0;
    for (int e = 0; e < NEXP; e++) {
        g_tilebase[e] = base;
        int nt = (g_cnt[e] + TS - 1) / TS;
        for (int i = 0; i < nt; i++) g_tile_expert[base / TS + i] = e;
        base += nt * TS;
    }
    g_ntiles = base / TS;
}
__global__ void k_scatter(const int* __restrict__ ids) {
    const int e = blockIdx.x, lane = threadIdx.x;
    int off = g_tilebase[e];
    for (int base = 0; base < NPAIR; base += 32) {
        int p = base + lane;
        bool m = (ids[p] == e);
        unsigned mask = __ballot_sync(0xffffffffu, m);
        if (m) {
            int r = off + __popc(mask & ((1u << lane) - 1u));
            g_rowtok[r] = p >> 3;
            g_slot[p] = r;
        }
        off += __popc(mask);
    }
}

// ---------------------------------------------------------------------------
// Gather + split hidden rows into padded [rows, H] bf16 hi/lo
// ---------------------------------------------------------------------------
__global__ void k_prepA(const float* __restrict__ hidden) {
    int idx = blockIdx.x * blockDim.x + threadIdx.x;   // over MAXROWS * 512
    int r  = idx >> 9;
    int c4 = idx & 511;
    if (r >= g_ntiles * TS) return;
    int tok = g_rowtok[r];
    float4 v = (tok >= 0) ? ((const float4*)hidden)[(size_t)tok * 512 + c4]
                          : make_float4(0.f, 0.f, 0.f, 0.f);
    uint2 h, l;
    split4(v, h, l);
    ((uint2*)g_Ah)[(size_t)r * 512 + c4] = h;
    ((uint2*)g_Al)[(size_t)r * 512 + c4] = l;
}

// ---------------------------------------------------------------------------
// HMMA grouped GEMM, 64x128 C-tile (identical mainloop to R11):
//   256 threads = 8 warps (2m x 4n), warp tile 32x32, BK=32, 2-stage smem,
//   B = raw fp32 weights, LDG.128 reg-double-buffered (16 floats/thread),
//   hi/lo bf16 split in regs, STS to 80B-stride smem; 3-term bf16x3 MMA.
// GATEUP=true: B rows interleaved gate/up (w1row = (col>>1)+(col&1)*F);
//   epilogue computes silu(gate)*up -> bf16 hi/lo activations directly.
// GATEUP=false: plain fp32 C output.
// ---------------------------------------------------------------------------
#define BUF_A   5120               //  64 rows * 80 B
#define BUF_B   10240              // 128 rows * 80 B
#define OFF_AH  0
#define OFF_AL  BUF_A
#define OFF_BH  (2 * BUF_A)
#define OFF_BL  (2 * BUF_A + BUF_B)
#define STAGE_B (2 * BUF_A + 2 * BUF_B)   // 30720
#define GEMM_SMEM (2 * STAGE_B)           // 61440

template<int NK, bool GATEUP>
__global__ __launch_bounds__(256, 2) void hmma_gemm(
    const __nv_bfloat16* __restrict__ Ah, const __nv_bfloat16* __restrict__ Al, int lda,
    const float* __restrict__ B, size_t bstride, int ldb,
    float* __restrict__ C, int ldc,
    __nv_bfloat16* __restrict__ Oh, __nv_bfloat16* __restrict__ Ol)
{
    const int mt = blockIdx.y;
    if (mt >= g_ntiles) return;
    const int e  = g_tile_expert[mt];
    const int n0 = blockIdx.x * 128;

    extern __shared__ char smem[];
    const uint32_t sb = smem_u32(smem);
    const int tid  = threadIdx.x;
    const int wid  = tid >> 5, lane = tid & 31;
    const int wr   = wid >> 2;          // 0..1 (m)
    const int wn   = wid & 3;           // 0..3 (n)

    // A loader: row = tid>>2 (0..63), 16B chunk q = tid&3
    const int arow = tid >> 2, aq = tid & 3;
    const __nv_bfloat16* pAh = Ah + (size_t)(mt * TS + arow) * lda + aq * 8;
    const __nv_bfloat16* pAl = Al + (size_t)(mt * TS + arow) * lda + aq * 8;
    const uint32_t adst = (uint32_t)arow * 80 + (uint32_t)aq * 16;
    // B loader (fp32): row = tid>>1 (0..127), half = tid&1 covers 16 floats.
    // Gate/up interleave for GEMM1: C column nn pulls w1 row (nn>>1)+(nn&1)*F.
    const int brow = tid >> 1, bhalf = tid & 1;
    const int ncol = n0 + brow;
    const int browg = GATEUP ? ((ncol >> 1) + (ncol & 1) * F_DIM) : ncol;
    const float* pB = B + (size_t)e * bstride + (size_t)browg * ldb + bhalf * 16;
    const uint32_t bdst = (uint32_t)brow * 80 + (uint32_t)bhalf * 32;

#define LOAD_A(s, k0) do {                                                      \
    uint32_t _g = sb + (s) * STAGE_B;                                           \
    CP_ASYNC16(_g + OFF_AH + adst, pAh + (k0));                                 \
    CP_ASYNC16(_g + OFF_AL + adst, pAl + (k0));                                 \
    CP_COMMIT();                                                                \
} while (0)

#define LOAD_B(dst, k0) do {                                                    \
    float4 _t0 = *(const float4*)(pB + (k0));                                   \
    float4 _t1 = *(const float4*)(pB + (k0) + 4);                               \
    float4 _t2 = *(const float4*)(pB + (k0) + 8);                               \
    float4 _t3 = *(const float4*)(pB + (k0) + 12);                              \
    dst[0]=_t0.x; dst[1]=_t0.y; dst[2]=_t0.z; dst[3]=_t0.w;                     \
    dst[4]=_t1.x; dst[5]=_t1.y; dst[6]=_t1.z; dst[7]=_t1.w;                     \
    dst[8]=_t2.x; dst[9]=_t2.y; dst[10]=_t2.z; dst[11]=_t2.w;                   \
    dst[12]=_t3.x; dst[13]=_t3.y; dst[14]=_t3.z; dst[15]=_t3.w;                 \
} while (0)

#define CONV_STS(s, bv) do {                                                    \
    uint32_t _g = sb + (s) * STAGE_B;                                           \
    uint32_t _hb[8], _lb[8];                                                    \
    _Pragma("unroll")                                                           \
    for (int _i = 0; _i < 8; _i++) {                                            \
        float _x = bv[2 * _i], _y = bv[2 * _i + 1];                             \
        __nv_bfloat16 _hx = __float2bfloat16(_x), _hy = __float2bfloat16(_y);   \
        _hb[_i] = pk(_hx, _hy);                                                 \
        _lb[_i] = pk(__float2bfloat16(_x - __bfloat162float(_hx)),              \
                     __float2bfloat16(_y - __bfloat162float(_hy)));             \
    }                                                                           \
    STSV4(_g + OFF_BH + bdst,      _hb[0], _hb[1], _hb[2], _hb[3]);             \
    STSV4(_g + OFF_BH + bdst + 16, _hb[4], _hb[5], _hb[6], _hb[7]);             \
    STSV4(_g + OFF_BL + bdst,      _lb[0], _lb[1], _lb[2], _lb[3]);             \
    STSV4(_g + OFF_BL + bdst + 16, _lb[4], _lb[5], _lb[6], _lb[7]);             \
} while (0)

    // ldmatrix lane offsets (within a 16x16 tile base), stride 80B
    const uint32_t aoff = (uint32_t)((((lane >> 3) & 1) * 8 + (lane & 7)) * 80 + (lane >> 4) * 16);
    const uint32_t boff = (uint32_t)(((lane >> 4) * 8 + (lane & 7)) * 80 + ((lane >> 3) & 1) * 16);

    float acc[2][4][4];
#pragma unroll
    for (int i = 0; i < 2; i++)
#pragma unroll
        for (int j = 0; j < 4; j++)
#pragma unroll
            for (int q = 0; q < 4; q++) acc[i][j][q] = 0.f;

    float bcur[16], bnxt[16];
    LOAD_B(bcur, 0);
    LOAD_A(0, 0);

    for (int kt = 0; kt < NK; kt++) {
        const int s = kt & 1;
        if (kt + 1 < NK) {
            LOAD_B(bnxt, (kt + 1) * 32);
            LOAD_A((kt + 1) & 1, (kt + 1) * 32);
            CP_WAIT(1);
        } else {
            CP_WAIT(0);
        }
        CONV_STS(s, bcur);
        __syncthreads();

        const uint32_t stg = sb + s * STAGE_B;
#pragma unroll
        for (int kk = 0; kk < 2; kk++) {
            const uint32_t ko = (uint32_t)kk * 32;
            uint32_t ah[2][4], al[2][4];
#pragma unroll
            for (int i = 0; i < 2; i++) {
                uint32_t ta = (uint32_t)(wr * 32 + i * 16) * 80 + ko;
                LDSM4(ah[i], stg + OFF_AH + ta + aoff);
                LDSM4(al[i], stg + OFF_AL + ta + aoff);
            }
            uint32_t bh[2][4], bl[2][4];
#pragma unroll
            for (int j = 0; j < 2; j++) {
                uint32_t tb = (uint32_t)(wn * 32 + j * 16) * 80 + ko;
                LDSM4(bh[j], stg + OFF_BH + tb + boff);
                LDSM4(bl[j], stg + OFF_BL + tb + boff);
            }
#pragma unroll
            for (int i = 0; i < 2; i++)
#pragma unroll
                for (int j = 0; j < 2; j++)
#pragma unroll
                    for (int s2 = 0; s2 < 2; s2++) {
                        MMA_BF16(acc[i][j * 2 + s2], ah[i], bh[j][2 * s2], bh[j][2 * s2 + 1]);
                        MMA_BF16(acc[i][j * 2 + s2], ah[i], bl[j][2 * s2], bl[j][2 * s2 + 1]);
                        MMA_BF16(acc[i][j * 2 + s2], al[i], bh[j][2 * s2], bh[j][2 * s2 + 1]);
                    }
        }
        __syncthreads();
#pragma unroll
        for (int i = 0; i < 16; i++) bcur[i] = bnxt[i];
    }
#undef LOAD_A
#undef LOAD_B
#undef CONV_STS

    const int r  = lane >> 2;
    const int c2 = (lane & 3) * 2;
    if (GATEUP) {
        // fused SiLU: acc pair (d0,d1) = (gate, up) at f = col>>1; (d2,d3) same at row+8
#pragma unroll
        for (int i = 0; i < 2; i++)
#pragma unroll
            for (int j = 0; j < 2; j++)
#pragma unroll
                for (int s2 = 0; s2 < 2; s2++) {
                    const float* q = acc[i][j * 2 + s2];
                    int col = n0 + wn * 32 + j * 16 + s2 * 8 + c2;   // even
                    int f   = col >> 1;
                    int row = mt * TS + wr * 32 + i * 16 + r;
                    float h0 = (q[0] / (1.f + __expf(-q[0]))) * q[1];
                    float h1 = (q[2] / (1.f + __expf(-q[2]))) * q[3];
                    __nv_bfloat16 hh0 = __float2bfloat16(h0);
                    __nv_bfloat16 hh1 = __float2bfloat16(h1);
                    Oh[(size_t)row * F_DIM + f] = hh0;
                    Ol[(size_t)row * F_DIM + f] = __float2bfloat16(h0 - __bfloat162float(hh0));
                    Oh[(size_t)(row + 8) * F_DIM + f] = hh1;
                    Ol[(size_t)(row + 8) * F_DIM + f] = __float2bfloat16(h1 - __bfloat162float(hh1));
                }
    } else {
#pragma unroll
        for (int i = 0; i < 2; i++)
#pragma unroll
            for (int j = 0; j < 2; j++)
#pragma unroll
                for (int s2 = 0; s2 < 2; s2++) {
                    float* p = C + (size_t)(mt * TS + wr * 32 + i * 16 + r) * ldc
                                 + n0 + wn * 32 + j * 16 + s2 * 8 + c2;
                    p[0] = acc[i][j * 2 + s2][0];
                    p[1] = acc[i][j * 2 + s2][1];
                    float* p2 = p + 8 * ldc;
                    p2[0] = acc[i][j * 2 + s2][2];
                    p2[1] = acc[i][j * 2 + s2][3];
                }
    }
}

// ---------------------------------------------------------------------------
// Combine: out[t][h] = sum_k tw[t,k] * y2[slot[t,k]][h]
// ---------------------------------------------------------------------------
__global__ void combine_kernel(const float* __restrict__ tw, float* __restrict__ out) {
    int idx = blockIdx.x * blockDim.x + threadIdx.x;
    int t  = idx / (H_DIM / 4);
    int hq = idx - t * (H_DIM / 4);
    if (t >= T_TOK) return;
    float4 acc = make_float4(0.f, 0.f, 0.f, 0.f);
#pragma unroll
    for (int k = 0; k < TOPK; k++) {
        int   s = g_slot[t * TOPK + k];
        float w = tw[t * TOPK + k];
        float4 v = *(const float4*)&g_y2[(size_t)s * H_DIM + hq * 4];
        acc.x += w * v.x; acc.y += w * v.y; acc.z += w * v.z; acc.w += w * v.w;
    }
    *(float4*)&out[(size_t)t * H_DIM + hq * 4] = acc;
}

// ---------------------------------------------------------------------------
extern "C" void kernel_launch(void* const* d_in, const int* in_sizes, int n_in,
                              void* d_out, int out_size) {
    const float* hidden = (const float*)d_in[0];
    const float* tw     = (const float*)d_in[1];
    const int*   ids    = (const int*)d_in[2];
    const float* w1     = (const float*)d_in[3];
    const float* w2     = (const float*)d_in[4];
    float*       out    = (float*)d_out;

    static void *p_Ah, *p_Al, *p_ah, *p_al, *p_y2;
    cudaGetSymbolAddress(&p_Ah, g_Ah);
    cudaGetSymbolAddress(&p_Al, g_Al);
    cudaGetSymbolAddress(&p_ah, g_acth);
    cudaGetSymbolAddress(&p_al, g_actl);
    cudaGetSymbolAddress(&p_y2, g_y2);

    cudaFuncSetAttribute(hmma_gemm<H_DIM / 32, true>,  cudaFuncAttributeMaxDynamicSharedMemorySize, GEMM_SMEM);
    cudaFuncSetAttribute(hmma_gemm<F_DIM / 32, false>, cudaFuncAttributeMaxDynamicSharedMemorySize, GEMM_SMEM);

    // dispatch + activation prep
    k_init<<<MAXROWS / 256, 256>>>();
    k_count<<<NPAIR / 256, 256>>>(ids);
    k_scan<<<1, 32>>>();
    k_scatter<<<NEXP, 32>>>(ids);
    k_prepA<<<MAXROWS * 512 / 256, 256>>>(hidden);

    // GEMM1 (+fused SiLU): act = silu(gate)*up from A @ w1^T, gate/up interleaved
    hmma_gemm<H_DIM / 32, true><<<dim3(F2_DIM / 128, MAXTILES), 256, GEMM_SMEM>>>(
        (const __nv_bfloat16*)p_Ah, (const __nv_bfloat16*)p_Al, H_DIM,
        w1, (size_t)F2_DIM * H_DIM, H_DIM, nullptr, 0,
        (__nv_bfloat16*)p_ah, (__nv_bfloat16*)p_al);

    // GEMM2: y2 = act @ w2^T  (K = 768; raw fp32 w2, split in-kernel)
    hmma_gemm<F_DIM / 32, false><<<dim3(H_DIM / 128, MAXTILES), 256, GEMM_SMEM>>>(
        (const __nv_bfloat16*)p_ah, (const __nv_bfloat16*)p_al, F_DIM,
        w2, (size_t)H_DIM * F_DIM, F_DIM, (float*)p_y2, H_DIM, nullptr, nullptr);

    combine_kernel<<<(T_TOK * H_DIM / 4 + 255) / 256, 256>>>(tw, out);
}

// round 17
// speedup vs baseline: 1.9030x; 1.2020x over previous
#include <cuda_runtime.h>
#include <cuda_fp16.h>
#include <cstdint>

// Problem constants: T=1024, H=2048, F=768, E=64, K=8
#define T_TOK   1024
#define H_DIM   2048
#define F_DIM   768
#define F2_DIM  1536
#define NEXP    64
#define TOPK    8
#define NPAIR   (T_TOK * TOPK)
#define TS      64                   // m-tile rows
#define MAXTILES 256                 // worst case: 64 + 8192/64 = 192
#define MAXROWS  16384

// ---------------------------------------------------------------------------
// Device-global scratch (allocation-free per harness rules)
// ---------------------------------------------------------------------------
__device__ int   g_cnt[NEXP];
__device__ int   g_tilebase[NEXP];
__device__ int   g_ntiles;
__device__ int   g_tile_expert[MAXTILES];
__device__ int   g_rowtok[MAXROWS];
__device__ int   g_slot[NPAIR];

__device__ __align__(256) __half g_Ah [(size_t)MAXROWS * H_DIM];
__device__ __align__(256) __half g_Al [(size_t)MAXROWS * H_DIM];
__device__ __align__(256) __half g_acth[(size_t)MAXROWS * F_DIM];
__device__ __align__(256) __half g_actl[(size_t)MAXROWS * F_DIM];
__device__ __align__(256) float g_y2 [(size_t)MAXROWS * H_DIM];

// ---------------------------------------------------------------------------
// Portable PTX helpers
// ---------------------------------------------------------------------------
__device__ __forceinline__ uint32_t smem_u32(const void* p) {
    uint32_t a;
    asm("{ .reg .u64 t; cvta.to.shared.u64 t, %1; cvt.u32.u64 %0, t; }" : "=r"(a) : "l"(p));
    return a;
}
#define CP_ASYNC16(dst_u32, src) \
    asm volatile("cp.async.cg.shared.global [%0], [%1], 16;" :: "r"(dst_u32), "l"(src))
#define CP_COMMIT() asm volatile("cp.async.commit_group;" ::: "memory")
#define CP_WAIT(n)  asm volatile("cp.async.wait_group %0;" :: "n"(n) : "memory")

#define LDSM4(r, addr) \
    asm volatile("ldmatrix.sync.aligned.m8n8.x4.shared.b16 {%0,%1,%2,%3}, [%4];" \
        : "=r"((r)[0]), "=r"((r)[1]), "=r"((r)[2]), "=r"((r)[3]) : "r"(addr))

#define MMA_FP16(d, a, b0v, b1v) \
    asm volatile("mma.sync.aligned.m16n8k16.row.col.f32.f16.f16.f32 " \
        "{%0,%1,%2,%3}, {%4,%5,%6,%7}, {%8,%9}, {%0,%1,%2,%3};" \
        : "+f"((d)[0]), "+f"((d)[1]), "+f"((d)[2]), "+f"((d)[3]) \
        : "r"((a)[0]), "r"((a)[1]), "r"((a)[2]), "r"((a)[3]), "r"(b0v), "r"(b1v))

#define STSV4(addr, r0, r1, r2, r3) \
    asm volatile("st.shared.v4.b32 [%0], {%1,%2,%3,%4};" \
        :: "r"(addr), "r"(r0), "r"(r1), "r"(r2), "r"(r3) : "memory")

// ---------------------------------------------------------------------------
// fp16 split helpers
// ---------------------------------------------------------------------------
__device__ __forceinline__ uint32_t pkh(__half a, __half b) {
    __half2 t(a, b);
    return *reinterpret_cast<uint32_t*>(&t);
}
__device__ __forceinline__ void split4h(float4 v, uint2& hi, uint2& lo) {
    __half h0 = __float2half_rn(v.x), h1 = __float2half_rn(v.y);
    __half h2 = __float2half_rn(v.z), h3 = __float2half_rn(v.w);
    __half l0 = __float2half_rn(v.x - __half2float(h0));
    __half l1 = __float2half_rn(v.y - __half2float(h1));
    __half l2 = __float2half_rn(v.z - __half2float(h2));
    __half l3 = __float2half_rn(v.w - __half2float(h3));
    hi = make_uint2(pkh(h0, h1), pkh(h2, h3));
    lo = make_uint2(pkh(l0, l1), pkh(l2, l3));
}

// ---------------------------------------------------------------------------
// Dispatch (counting sort, deterministic)
// ---------------------------------------------------------------------------
__global__ void k_init() {
    int i = blockIdx.x * blockDim.x + threadIdx.x;
    if (i < MAXROWS) g_rowtok[i] = -1;
    if (i < NEXP)    g_cnt[i] = 0;
}
__global__ void k_count(const int* __restrict__ ids) {
    int p = blockIdx.x * blockDim.x + threadIdx.x;
    if (p < NPAIR) atomicAdd(&g_cnt[ids[p]], 1);
}
__global__ void k_scan() {
    if (threadIdx.x != 0 || blockIdx.x != 0) return;
    int base = 0;
    for (int e = 0; e < NEXP; e++) {
        g_tilebase[e] = base;
        int nt = (g_cnt[e] + TS - 1) / TS;
        for (int i = 0; i < nt; i++) g_tile_expert[base / TS + i] = e;
        base += nt * TS;
    }
    g_ntiles = base / TS;
}
__global__ void k_scatter(const int* __restrict__ ids) {
    const int e = blockIdx.x, lane = threadIdx.x;
    int off = g_tilebase[e];
    for (int base = 0; base < NPAIR; base += 32) {
        int p = base + lane;
        bool m = (ids[p] == e);
        unsigned mask = __ballot_sync(0xffffffffu, m);
        if (m) {
            int r = off + __popc(mask & ((1u << lane) - 1u));
            g_rowtok[r] = p >> 3;
            g_slot[p] = r;
        }
        off += __popc(mask);
    }
}

// ---------------------------------------------------------------------------
// Gather + split hidden rows into padded [rows, H] fp16 hi/lo
// ---------------------------------------------------------------------------
__global__ void k_prepA(const float* __restrict__ hidden) {
    int idx = blockIdx.x * blockDim.x + threadIdx.x;   // over MAXROWS * 512
    int r  = idx >> 9;
    int c4 = idx & 511;
    if (r >= g_ntiles * TS) return;
    int tok = g_rowtok[r];
    float4 v = (tok >= 0) ? ((const float4*)hidden)[(size_t)tok * 512 + c4]
                          : make_float4(0.f, 0.f, 0.f, 0.f);
    uint2 h, l;
    split4h(v, h, l);
    ((uint2*)g_Ah)[(size_t)r * 512 + c4] = h;
    ((uint2*)g_Al)[(size_t)r * 512 + c4] = l;
}

// ---------------------------------------------------------------------------
// HMMA grouped GEMM, 64x128 C-tile:
//   256 threads = 8 warps (2m x 4n), warp tile 32x32, BK=32, 2-stage smem.
//   A = fp16 hi/lo (2-term), cp.async. B = raw fp32 weights, LDG.128
//   reg-double-buffered, converted to SINGLE fp16 in regs, STS to smem.
//   2-term fp16x2: Ah*B + Al*B, fp32 accum.
// GATEUP=true: B rows interleaved gate/up; epilogue silu(gate)*up ->
//   fp16 hi/lo activations directly.
// ---------------------------------------------------------------------------
#define BUF_A   5120               //  64 rows * 80 B
#define BUF_B   10240              // 128 rows * 80 B
#define OFF_AH  0
#define OFF_AL  BUF_A
#define OFF_BH  (2 * BUF_A)
#define STAGE_B (2 * BUF_A + BUF_B)       // 20480
#define GEMM_SMEM (2 * STAGE_B)           // 40960

template<int NK, bool GATEUP>
__global__ __launch_bounds__(256, 2) void hmma_gemm(
    const __half* __restrict__ Ah, const __half* __restrict__ Al, int lda,
    const float* __restrict__ B, size_t bstride, int ldb,
    float* __restrict__ C, int ldc,
    __half* __restrict__ Oh, __half* __restrict__ Ol)
{
    const int mt = blockIdx.y;
    if (mt >= g_ntiles) return;
    const int e  = g_tile_expert[mt];
    const int n0 = blockIdx.x * 128;

    extern __shared__ char smem[];
    const uint32_t sb = smem_u32(smem);
    const int tid  = threadIdx.x;
    const int wid  = tid >> 5, lane = tid & 31;
    const int wr   = wid >> 2;          // 0..1 (m)
    const int wn   = wid & 3;           // 0..3 (n)

    // A loader: row = tid>>2 (0..63), 16B chunk q = tid&3
    const int arow = tid >> 2, aq = tid & 3;
    const __half* pAh = Ah + (size_t)(mt * TS + arow) * lda + aq * 8;
    const __half* pAl = Al + (size_t)(mt * TS + arow) * lda + aq * 8;
    const uint32_t adst = (uint32_t)arow * 80 + (uint32_t)aq * 16;
    // B loader (fp32): row = tid>>1 (0..127), half = tid&1 covers 16 floats.
    // Gate/up interleave for GEMM1: C column nn pulls w1 row (nn>>1)+(nn&1)*F.
    const int brow = tid >> 1, bhalf = tid & 1;
    const int ncol = n0 + brow;
    const int browg = GATEUP ? ((ncol >> 1) + (ncol & 1) * F_DIM) : ncol;
    const float* pB = B + (size_t)e * bstride + (size_t)browg * ldb + bhalf * 16;
    const uint32_t bdst = (uint32_t)brow * 80 + (uint32_t)bhalf * 32;

#define LOAD_A(s, k0) do {                                                      \
    uint32_t _g = sb + (s) * STAGE_B;                                           \
    CP_ASYNC16(_g + OFF_AH + adst, pAh + (k0));                                 \
    CP_ASYNC16(_g + OFF_AL + adst, pAl + (k0));                                 \
    CP_COMMIT();                                                                \
} while (0)

#define LOAD_B(dst, k0) do {                                                    \
    float4 _t0 = *(const float4*)(pB + (k0));                                   \
    float4 _t1 = *(const float4*)(pB + (k0) + 4);                               \
    float4 _t2 = *(const float4*)(pB + (k0) + 8);                               \
    float4 _t3 = *(const float4*)(pB + (k0) + 12);                              \
    dst[0]=_t0.x; dst[1]=_t0.y; dst[2]=_t0.z; dst[3]=_t0.w;                     \
    dst[4]=_t1.x; dst[5]=_t1.y; dst[6]=_t1.z; dst[7]=_t1.w;                     \
    dst[8]=_t2.x; dst[9]=_t2.y; dst[10]=_t2.z; dst[11]=_t2.w;                   \
    dst[12]=_t3.x; dst[13]=_t3.y; dst[14]=_t3.z; dst[15]=_t3.w;                 \
} while (0)

#define CONV_STS(s, bv) do {                                                    \
    uint32_t _g = sb + (s) * STAGE_B;                                           \
    uint32_t _hb[8];                                                            \
    _Pragma("unroll")                                                           \
    for (int _i = 0; _i < 8; _i++) {                                            \
        _hb[_i] = pkh(__float2half_rn(bv[2 * _i]), __float2half_rn(bv[2 * _i + 1])); \
    }                                                                           \
    STSV4(_g + OFF_BH + bdst,      _hb[0], _hb[1], _hb[2], _hb[3]);             \
    STSV4(_g + OFF_BH + bdst + 16, _hb[4], _hb[5], _hb[6], _hb[7]);             \
} while (0)

    // ldmatrix lane offsets (within a 16x16 tile base), stride 80B
    const uint32_t aoff = (uint32_t)((((lane >> 3) & 1) * 8 + (lane & 7)) * 80 + (lane >> 4) * 16);
    const uint32_t boff = (uint32_t)(((lane >> 4) * 8 + (lane & 7)) * 80 + ((lane >> 3) & 1) * 16);

    float acc[2][4][4];
#pragma unroll
    for (int i = 0; i < 2; i++)
#pragma unroll
        for (int j = 0; j < 4; j++)
#pragma unroll
            for (int q = 0; q < 4; q++) acc[i][j][q] = 0.f;

    float bcur[16], bnxt[16];
    LOAD_B(bcur, 0);
    LOAD_A(0, 0);

    for (int kt = 0; kt < NK; kt++) {
        const int s = kt & 1;
        if (kt + 1 < NK) {
            LOAD_B(bnxt, (kt + 1) * 32);
            LOAD_A((kt + 1) & 1, (kt + 1) * 32);
            CP_WAIT(1);
        } else {
            CP_WAIT(0);
        }
        CONV_STS(s, bcur);
        __syncthreads();

        const uint32_t stg = sb + s * STAGE_B;
#pragma unroll
        for (int kk = 0; kk < 2; kk++) {
            const uint32_t ko = (uint32_t)kk * 32;
            uint32_t ah[2][4], al[2][4];
#pragma unroll
            for (int i = 0; i < 2; i++) {
                uint32_t ta = (uint32_t)(wr * 32 + i * 16) * 80 + ko;
                LDSM4(ah[i], stg + OFF_AH + ta + aoff);
                LDSM4(al[i], stg + OFF_AL + ta + aoff);
            }
            uint32_t bh[2][4];
#pragma unroll
            for (int j = 0; j < 2; j++) {
                uint32_t tb = (uint32_t)(wn * 32 + j * 16) * 80 + ko;
                LDSM4(bh[j], stg + OFF_BH + tb + boff);
            }
#pragma unroll
            for (int i = 0; i < 2; i++)
#pragma unroll
                for (int j = 0; j < 2; j++)
#pragma unroll
                    for (int s2 = 0; s2 < 2; s2++) {
                        MMA_FP16(acc[i][j * 2 + s2], ah[i], bh[j][2 * s2], bh[j][2 * s2 + 1]);
                        MMA_FP16(acc[i][j * 2 + s2], al[i], bh[j][2 * s2], bh[j][2 * s2 + 1]);
                    }
        }
        __syncthreads();
#pragma unroll
        for (int i = 0; i < 16; i++) bcur[i] = bnxt[i];
    }
#undef LOAD_A
#undef LOAD_B
#undef CONV_STS

    const int r  = lane >> 2;
    const int c2 = (lane & 3) * 2;
    if (GATEUP) {
        // fused SiLU: acc pair (d0,d1) = (gate, up) at f = col>>1; (d2,d3) same at row+8
#pragma unroll
        for (int i = 0; i < 2; i++)
#pragma unroll
            for (int j = 0; j < 2; j++)
#pragma unroll
                for (int s2 = 0; s2 < 2; s2++) {
                    const float* q = acc[i][j * 2 + s2];
                    int col = n0 + wn * 32 + j * 16 + s2 * 8 + c2;   // even
                    int f   = col >> 1;
                    int row = mt * TS + wr * 32 + i * 16 + r;
                    float h0 = (q[0] / (1.f + __expf(-q[0]))) * q[1];
                    float h1 = (q[2] / (1.f + __expf(-q[2]))) * q[3];
                    __half hh0 = __float2half_rn(h0);
                    __half hh1 = __float2half_rn(h1);
                    Oh[(size_t)row * F_DIM + f] = hh0;
                    Ol[(size_t)row * F_DIM + f] = __float2half_rn(h0 - __half2float(hh0));
                    Oh[(size_t)(row + 8) * F_DIM + f] = hh1;
                    Ol[(size_t)(row + 8) * F_DIM + f] = __float2half_rn(h1 - __half2float(hh1));
                }
    } else {
#pragma unroll
        for (int i = 0; i < 2; i++)
#pragma unroll
            for (int j = 0; j < 2; j++)
#pragma unroll
                for (int s2 = 0; s2 < 2; s2++) {
                    float* p = C + (size_t)(mt * TS + wr * 32 + i * 16 + r) * ldc
                                 + n0 + wn * 32 + j * 16 + s2 * 8 + c2;
                    p[0] = acc[i][j * 2 + s2][0];
                    p[1] = acc[i][j * 2 + s2][1];
                    float* p2 = p + 8 * ldc;
                    p2[0] = acc[i][j * 2 + s2][2];
                    p2[1] = acc[i][j * 2 + s2][3];
                }
    }
}

// ---------------------------------------------------------------------------
// Combine: out[t][h] = sum_k tw[t,k] * y2[slot[t,k]][h]
// ---------------------------------------------------------------------------
__global__ void combine_kernel(const float* __restrict__ tw, float* __restrict__ out) {
    int idx = blockIdx.x * blockDim.x + threadIdx.x;
    int t  = idx / (H_DIM / 4);
    int hq = idx - t * (H_DIM / 4);
    if (t >= T_TOK) return;
    float4 acc = make_float4(0.f, 0.f, 0.f, 0.f);
#pragma unroll
    for (int k = 0; k < TOPK; k++) {
        int   s = g_slot[t * TOPK + k];
        float w = tw[t * TOPK + k];
        float4 v = *(const float4*)&g_y2[(size_t)s * H_DIM + hq * 4];
        acc.x += w * v.x; acc.y += w * v.y; acc.z += w * v.z; acc.w += w * v.w;
    }
    *(float4*)&out[(size_t)t * H_DIM + hq * 4] = acc;
}

// ---------------------------------------------------------------------------
extern "C" void kernel_launch(void* const* d_in, const int* in_sizes, int n_in,
                              void* d_out, int out_size) {
    const float* hidden = (const float*)d_in[0];
    const float* tw     = (const float*)d_in[1];
    const int*   ids    = (const int*)d_in[2];
    const float* w1     = (const float*)d_in[3];
    const float* w2     = (const float*)d_in[4];
    float*       out    = (float*)d_out;

    static void *p_Ah, *p_Al, *p_ah, *p_al, *p_y2;
    cudaGetSymbolAddress(&p_Ah, g_Ah);
    cudaGetSymbolAddress(&p_Al, g_Al);
    cudaGetSymbolAddress(&p_ah, g_acth);
    cudaGetSymbolAddress(&p_al, g_actl);
    cudaGetSymbolAddress(&p_y2, g_y2);

    cudaFuncSetAttribute(hmma_gemm<H_DIM / 32, true>,  cudaFuncAttributeMaxDynamicSharedMemorySize, GEMM_SMEM);
    cudaFuncSetAttribute(hmma_gemm<F_DIM / 32, false>, cudaFuncAttributeMaxDynamicSharedMemorySize, GEMM_SMEM);

    // dispatch + activation prep
    k_init<<<MAXROWS / 256, 256>>>();
    k_count<<<NPAIR / 256, 256>>>(ids);
    k_scan<<<1, 32>>>();
    k_scatter<<<NEXP, 32>>>(ids);
    k_prepA<<<MAXROWS * 512 / 256, 256>>>(hidden);

    // GEMM1 (+fused SiLU): act = silu(gate)*up from A @ w1^T, gate/up interleaved
    hmma_gemm<H_DIM / 32, true><<<dim3(F2_DIM / 128, MAXTILES), 256, GEMM_SMEM>>>(
        (const __half*)p_Ah, (const __half*)p_Al, H_DIM,
        w1, (size_t)F2_DIM * H_DIM, H_DIM, nullptr, 0,
        (__half*)p_ah, (__half*)p_al);

    // GEMM2: y2 = act @ w2^T  (K = 768; raw fp32 w2 -> single fp16 in-kernel)
    hmma_gemm<F_DIM / 32, false><<<dim3(H_DIM / 128, MAXTILES), 256, GEMM_SMEM>>>(
        (const __half*)p_ah, (const __half*)p_al, F_DIM,
        w2, (size_t)H_DIM * F_DIM, F_DIM, (float*)p_y2, H_DIM, nullptr, nullptr);

    combine_kernel<<<(T_TOK * H_DIM / 4 + 255) / 256, 256>>>(tw, out);
}